// round 1
// baseline (speedup 1.0000x reference)
#include <cuda_runtime.h>
#include <cuda_bf16.h>
#include <math.h>

// ---------------- problem constants ----------------
#define NN      10000     // nodes
#define EE      160000    // edges (without self loops)
#define ETOT    170000    // edges + self loops
#define NH      8         // heads
#define C1      30
#define C2      64
#define HC1     240       // NH*C1
#define HC2     512       // NH*C2
#define FIN     512
#define NCLS    64

// ---------------- device scratch (no allocation allowed) ----------------
__device__ int   g_flag32;                 // 1 => edge_index is int32
__device__ int   g_src[EE];
__device__ int   g_dst[EE];
__device__ int   g_cnt[NN];
__device__ int   g_off[NN + 1];
__device__ int   g_cur[NN];
__device__ int   g_csr[ETOT];              // src node per (dst-sorted) edge
__device__ float g_feat1[NN * HC1];        // x @ W1
__device__ float g_as1[NN * NH];
__device__ float g_ad1[NN * NH];
__device__ float g_h1[NN * HC1];           // elu(gat1)
__device__ float g_feat2[NN * HC2];        // h1 @ W2
__device__ float g_as2[NN * NH];
__device__ float g_ad2[NN * NH];

// ---------------- helpers ----------------
__device__ __forceinline__ unsigned encodeF(float f) {
    unsigned u = __float_as_uint(f);
    return (u & 0x80000000u) ? ~u : (u | 0x80000000u);
}
__device__ __forceinline__ float decodeF(unsigned e) {
    return (e & 0x80000000u) ? __uint_as_float(e ^ 0x80000000u)
                             : __uint_as_float(~e);
}

// ---------------- graph preprocessing ----------------
__global__ void k_init() {
    int i = blockIdx.x * blockDim.x + threadIdx.x;
    if (i < NN) g_cnt[i] = 1;              // self loop
    if (i == 0) g_flag32 = 0;
}

__global__ void k_detect(const int* __restrict__ e32) {
    int i = blockIdx.x * blockDim.x + threadIdx.x;
    if (i < EE) {
        // safe: reads within first 320000 int32 words either way
        if (e32[2 * i + 1] != 0) atomicOr(&g_flag32, 1);
    }
}

__global__ void k_convert(const void* __restrict__ eraw) {
    int i = blockIdx.x * blockDim.x + threadIdx.x;
    if (i >= EE) return;
    if (g_flag32) {
        const int* p = (const int*)eraw;
        g_src[i] = p[i];
        g_dst[i] = p[EE + i];
    } else {
        const long long* p = (const long long*)eraw;
        g_src[i] = (int)p[i];
        g_dst[i] = (int)p[EE + i];
    }
}

__global__ void k_count() {
    int i = blockIdx.x * blockDim.x + threadIdx.x;
    if (i < EE) atomicAdd(&g_cnt[g_dst[i]], 1);
}

__global__ void k_scan() {
    __shared__ int ps[257];
    const int CHUNK = 40;                  // 256*40 >= NN
    int t = threadIdx.x;
    int s = 0;
    for (int k = 0; k < CHUNK; k++) {
        int idx = t * CHUNK + k;
        if (idx < NN) s += g_cnt[idx];
    }
    ps[t] = s;
    __syncthreads();
    if (t == 0) {
        int run = 0;
        for (int i = 0; i < 256; i++) { int tmp = ps[i]; ps[i] = run; run += tmp; }
        ps[256] = run;
    }
    __syncthreads();
    int run = ps[t];
    for (int k = 0; k < CHUNK; k++) {
        int idx = t * CHUNK + k;
        if (idx < NN) {
            g_off[idx] = run;
            g_cur[idx] = run;
            run += g_cnt[idx];
        }
    }
    if (t == 0) g_off[NN] = ps[256];
}

__global__ void k_scatter() {
    int i = blockIdx.x * blockDim.x + threadIdx.x;
    if (i >= ETOT) return;
    int d, s;
    if (i < EE) { d = g_dst[i]; s = g_src[i]; }
    else        { d = i - EE;   s = d; }
    int pos = atomicAdd(&g_cur[d], 1);
    g_csr[pos] = s;
}

// ---------------- SGEMM: C[M,Nc] = A[M,K] @ B[K,Nc] (+bias) ----------------
// BM=128, BN=64, BK=16, TM=8, TN=4, 256 threads. Requires K % 16 == 0.
__global__ __launch_bounds__(256) void k_sgemm(
    const float* __restrict__ A, const float* __restrict__ B,
    float* __restrict__ C, int M, int Nc, int K,
    const float* __restrict__ bias)
{
    const int BM = 128, BN = 64, BK = 16, TM = 8, TN = 4;
    __shared__ float As[BK][BM + 4];
    __shared__ float Bs[BK][BN];
    int tid = threadIdx.x;
    int tx = tid % (BN / TN);   // 0..15
    int ty = tid / (BN / TN);   // 0..15
    int row0 = blockIdx.y * BM;
    int col0 = blockIdx.x * BN;
    float acc[TM][TN];
#pragma unroll
    for (int i = 0; i < TM; i++)
#pragma unroll
        for (int j = 0; j < TN; j++) acc[i][j] = 0.f;

    for (int k0 = 0; k0 < K; k0 += BK) {
        // A tile: 128x16, float4 loads, 2 per thread
#pragma unroll
        for (int v = 0; v < 2; v++) {
            int f4 = tid + v * 256;          // 512 float4s
            int r  = f4 >> 2;                // 4 float4 per row
            int c4 = f4 & 3;
            float4 val = make_float4(0.f, 0.f, 0.f, 0.f);
            if (row0 + r < M)
                val = *(const float4*)(A + (size_t)(row0 + r) * K + k0 + c4 * 4);
            As[c4 * 4 + 0][r] = val.x;
            As[c4 * 4 + 1][r] = val.y;
            As[c4 * 4 + 2][r] = val.z;
            As[c4 * 4 + 3][r] = val.w;
        }
        // B tile: 16x64, scalar guarded loads, 4 per thread
#pragma unroll
        for (int v = 0; v < 4; v++) {
            int i = tid + v * 256;
            int r = i >> 6, c = i & 63;
            float val = 0.f;
            if (col0 + c < Nc)
                val = B[(size_t)(k0 + r) * Nc + col0 + c];
            Bs[r][c] = val;
        }
        __syncthreads();
#pragma unroll
        for (int k = 0; k < BK; k++) {
            float a[TM], b[TN];
#pragma unroll
            for (int i = 0; i < TM; i++) a[i] = As[k][ty * TM + i];
#pragma unroll
            for (int j = 0; j < TN; j++) b[j] = Bs[k][tx * TN + j];
#pragma unroll
            for (int i = 0; i < TM; i++)
#pragma unroll
                for (int j = 0; j < TN; j++) acc[i][j] += a[i] * b[j];
        }
        __syncthreads();
    }
#pragma unroll
    for (int i = 0; i < TM; i++) {
        int r = row0 + ty * TM + i;
        if (r >= M) continue;
#pragma unroll
        for (int j = 0; j < TN; j++) {
            int c = col0 + tx * TN + j;
            if (c >= Nc) continue;
            float v = acc[i][j];
            if (bias) v += bias[c];
            C[(size_t)r * Nc + c] = v;
        }
    }
}

// ---------------- attention projections: asrc/adst per (node, head) ----------------
template<int C>
__global__ void k_att(const float* __restrict__ feat,
                      const float* __restrict__ a_src,
                      const float* __restrict__ a_dst,
                      float* __restrict__ asrc,
                      float* __restrict__ adst)
{
    int idx = blockIdx.x * blockDim.x + threadIdx.x;
    if (idx >= NN * NH) return;
    int n = idx >> 3, h = idx & 7;
    const float* fr = feat + (size_t)n * (NH * C) + h * C;
    float ss = 0.f, sd = 0.f;
#pragma unroll
    for (int c = 0; c < C; c++) {
        float f = fr[c];
        ss += f * a_src[h * C + c];
        sd += f * a_dst[h * C + c];
    }
    asrc[idx] = ss;
    adst[idx] = sd;
}

// ---------------- per-destination GAT aggregation ----------------
// One 256-thread block per destination node. 3 passes: max, exp-sum, gather.
template<int C, bool ELU>
__global__ __launch_bounds__(256) void k_agg(
    const float* __restrict__ feat,
    const float* __restrict__ asrc,
    const float* __restrict__ adst,
    const float* __restrict__ bias,
    float* __restrict__ out)
{
    const int HC = NH * C;
    __shared__ float    s_adst[NH];
    __shared__ unsigned s_max[NH];
    __shared__ float    s_sum[NH];
    __shared__ int      s_src[64];
    __shared__ float    s_w[64 * NH];

    int n = blockIdx.x, tid = threadIdx.x;
    if (tid < NH) {
        s_adst[tid] = adst[n * NH + tid];
        s_max[tid]  = encodeF(-3.4e38f);
        s_sum[tid]  = 0.f;
    }
    __syncthreads();

    int base = g_off[n];
    int deg  = g_off[n + 1] - base;

    // pass 1: per-head max of leaky_relu(asrc[src]+adst[dst])
    for (int i = tid; i < deg * NH; i += 256) {
        int j = i >> 3, h = i & 7;
        int s = g_csr[base + j];
        float al = asrc[s * NH + h] + s_adst[h];
        al = al > 0.f ? al : 0.2f * al;
        atomicMax(&s_max[h], encodeF(al));
    }
    __syncthreads();

    // pass 2: per-head sum of exp(alpha - max)
    for (int i = tid; i < deg * NH; i += 256) {
        int j = i >> 3, h = i & 7;
        int s = g_csr[base + j];
        float al = asrc[s * NH + h] + s_adst[h];
        al = al > 0.f ? al : 0.2f * al;
        float ex = __expf(al - decodeF(s_max[h]));
        atomicAdd(&s_sum[h], ex);
    }
    __syncthreads();

    // pass 3: staged weighted gather
    int c0 = tid, c1 = tid + 256;
    int h0 = c0 / C, h1 = c1 / C;
    float acc0 = 0.f, acc1 = 0.f;

    for (int j0 = 0; j0 < deg; j0 += 64) {
        int nch = min(64, deg - j0);
        if (tid < nch) s_src[tid] = g_csr[base + j0 + tid];
        for (int i = tid; i < nch * NH; i += 256) {
            int j = i >> 3, h = i & 7;
            int s = g_csr[base + j0 + j];
            float al = asrc[s * NH + h] + s_adst[h];
            al = al > 0.f ? al : 0.2f * al;
            float w = __expf(al - decodeF(s_max[h])) / (s_sum[h] + 1e-16f);
            s_w[(j << 3) + h] = w;
        }
        __syncthreads();
        for (int j = 0; j < nch; j++) {
            const float* fr = feat + (size_t)s_src[j] * HC;
            if (c0 < HC) acc0 += s_w[(j << 3) + h0] * fr[c0];
            if (HC > 256 && c1 < HC) acc1 += s_w[(j << 3) + h1] * fr[c1];
        }
        __syncthreads();
    }

    if (c0 < HC) {
        float v = acc0 + bias[c0];
        if (ELU) v = v > 0.f ? v : (__expf(v) - 1.f);
        out[(size_t)n * HC + c0] = v;
    }
    if (HC > 256 && c1 < HC) {
        float v = acc1 + bias[c1];
        if (ELU) v = v > 0.f ? v : (__expf(v) - 1.f);
        out[(size_t)n * HC + c1] = v;
    }
}

// ---------------- launch ----------------
extern "C" void kernel_launch(void* const* d_in, const int* in_sizes, int n_in,
                              void* d_out, int out_size)
{
    const float* x    = (const float*)d_in[0];
    const void*  eidx = d_in[1];
    const float* W1   = (const float*)d_in[2];
    const float* a1s  = (const float*)d_in[3];
    const float* a1d  = (const float*)d_in[4];
    const float* b1   = (const float*)d_in[5];
    const float* W2   = (const float*)d_in[6];
    const float* a2s  = (const float*)d_in[7];
    const float* a2d  = (const float*)d_in[8];
    const float* b2   = (const float*)d_in[9];
    const float* Wlin = (const float*)d_in[10];
    const float* blin = (const float*)d_in[11];

    float* out_cls = (float*)d_out;                 // [NN, NCLS]
    float* out_h   = out_cls + (size_t)NN * NCLS;   // [NN, HC2]

    // symbol addresses for scratch used by generic kernels
    void *p_feat1, *p_as1, *p_ad1, *p_h1, *p_feat2, *p_as2, *p_ad2;
    cudaGetSymbolAddress(&p_feat1, g_feat1);
    cudaGetSymbolAddress(&p_as1,   g_as1);
    cudaGetSymbolAddress(&p_ad1,   g_ad1);
    cudaGetSymbolAddress(&p_h1,    g_h1);
    cudaGetSymbolAddress(&p_feat2, g_feat2);
    cudaGetSymbolAddress(&p_as2,   g_as2);
    cudaGetSymbolAddress(&p_ad2,   g_ad2);

    const int T = 256;

    // --- graph preprocessing ---
    k_init   <<<(NN   + T - 1) / T, T>>>();
    k_detect <<<(EE   + T - 1) / T, T>>>((const int*)eidx);
    k_convert<<<(EE   + T - 1) / T, T>>>(eidx);
    k_count  <<<(EE   + T - 1) / T, T>>>();
    k_scan   <<<1, 256>>>();
    k_scatter<<<(ETOT + T - 1) / T, T>>>();

    // --- layer 1 ---
    {
        dim3 grid((HC1 + 63) / 64, (NN + 127) / 128);
        k_sgemm<<<grid, 256>>>(x, W1, (float*)p_feat1, NN, HC1, FIN, nullptr);
    }
    k_att<C1><<<(NN * NH + T - 1) / T, T>>>((const float*)p_feat1, a1s, a1d,
                                            (float*)p_as1, (float*)p_ad1);
    k_agg<C1, true><<<NN, 256>>>((const float*)p_feat1, (const float*)p_as1,
                                 (const float*)p_ad1, b1, (float*)p_h1);

    // --- layer 2 ---
    {
        dim3 grid((HC2 + 63) / 64, (NN + 127) / 128);
        k_sgemm<<<grid, 256>>>((const float*)p_h1, W2, (float*)p_feat2, NN, HC2, HC1, nullptr);
    }
    k_att<C2><<<(NN * NH + T - 1) / T, T>>>((const float*)p_feat2, a2s, a2d,
                                            (float*)p_as2, (float*)p_ad2);
    k_agg<C2, false><<<NN, 256>>>((const float*)p_feat2, (const float*)p_as2,
                                  (const float*)p_ad2, b2, out_h);

    // --- final linear: out = h @ Wlin + blin ---
    {
        dim3 grid((NCLS + 63) / 64, (NN + 127) / 128);
        k_sgemm<<<grid, 256>>>(out_h, Wlin, out_cls, NN, NCLS, HC2, blin);
    }
}

// round 3
// speedup vs baseline: 1.1706x; 1.1706x over previous
#include <cuda_runtime.h>
#include <cuda_bf16.h>
#include <mma.h>
#include <math.h>
#include <cstdint>

using namespace nvcuda;

// ---------------- problem constants ----------------
#define NN      10000     // nodes
#define EE      160000    // edges (without self loops)
#define ETOT    170000    // edges + self loops
#define NH      8         // heads
#define C1      30
#define C2      64
#define HC1     240       // NH*C1
#define HC2     512       // NH*C2
#define FIN     512
#define NCLS    64

// ---------------- device scratch (no allocation allowed) ----------------
__device__ int   g_flag32;
__device__ int   g_src[EE];
__device__ int   g_dst[EE];
__device__ int   g_cnt[NN];
__device__ int   g_off[NN + 1];
__device__ int   g_cur[NN];
__device__ int   g_csr[ETOT];
__device__ float g_feat1[NN * HC1];
__device__ float g_as1[NN * NH];
__device__ float g_ad1[NN * NH];
__device__ float g_h1[NN * HC1];
__device__ float g_feat2[NN * HC2];
__device__ float g_as2[NN * NH];
__device__ float g_ad2[NN * NH];

// ---------------- helpers ----------------
__device__ __forceinline__ unsigned encodeF(float f) {
    unsigned u = __float_as_uint(f);
    return (u & 0x80000000u) ? ~u : (u | 0x80000000u);
}
__device__ __forceinline__ float decodeF(unsigned e) {
    return (e & 0x80000000u) ? __uint_as_float(e ^ 0x80000000u)
                             : __uint_as_float(~e);
}
__device__ __forceinline__ float to_tf32(float f) {
    float o;
    asm("cvt.rna.tf32.f32 %0, %1;" : "=f"(o) : "f"(f));
    return o;
}

// ---------------- graph preprocessing ----------------
__global__ void k_init() {
    int i = blockIdx.x * blockDim.x + threadIdx.x;
    if (i < NN) g_cnt[i] = 1;
    if (i == 0) g_flag32 = 0;
}
__global__ void k_detect(const int* __restrict__ e32) {
    int i = blockIdx.x * blockDim.x + threadIdx.x;
    if (i < EE && e32[2 * i + 1] != 0) atomicOr(&g_flag32, 1);
}
__global__ void k_convert(const void* __restrict__ eraw) {
    int i = blockIdx.x * blockDim.x + threadIdx.x;
    if (i >= EE) return;
    if (g_flag32) {
        const int* p = (const int*)eraw;
        g_src[i] = p[i];
        g_dst[i] = p[EE + i];
    } else {
        const long long* p = (const long long*)eraw;
        g_src[i] = (int)p[i];
        g_dst[i] = (int)p[EE + i];
    }
}
__global__ void k_count() {
    int i = blockIdx.x * blockDim.x + threadIdx.x;
    if (i < EE) atomicAdd(&g_cnt[g_dst[i]], 1);
}
__global__ void k_scan() {
    __shared__ int ps[257];
    const int CHUNK = 40;
    int t = threadIdx.x;
    int s = 0;
    for (int k = 0; k < CHUNK; k++) {
        int idx = t * CHUNK + k;
        if (idx < NN) s += g_cnt[idx];
    }
    ps[t] = s;
    __syncthreads();
    if (t == 0) {
        int run = 0;
        for (int i = 0; i < 256; i++) { int tmp = ps[i]; ps[i] = run; run += tmp; }
        ps[256] = run;
    }
    __syncthreads();
    int run = ps[t];
    for (int k = 0; k < CHUNK; k++) {
        int idx = t * CHUNK + k;
        if (idx < NN) {
            g_off[idx] = run;
            g_cur[idx] = run;
            run += g_cnt[idx];
        }
    }
    if (t == 0) g_off[NN] = ps[256];
}
__global__ void k_scatter() {
    int i = blockIdx.x * blockDim.x + threadIdx.x;
    if (i >= ETOT) return;
    int d, s;
    if (i < EE) { d = g_dst[i]; s = g_src[i]; }
    else        { d = i - EE;   s = d; }
    int pos = atomicAdd(&g_cur[d], 1);
    g_csr[pos] = s;
}

// ---------------- tf32 tensor-core GEMM via mma.sync (wmma) ----------------
// C[M,Nc] = A[M,K] @ B[K,Nc]. CTA tile 128x64, BK=16, 8 warps in 4x2,
// warp tile 32x32 (2x2 wmma m16n16k8 fragments). K must be a multiple of 16.
__global__ __launch_bounds__(256) void k_gemm_wmma(
    const float* __restrict__ A, const float* __restrict__ B,
    float* __restrict__ C, int M, int Nc, int K)
{
    const int LDA = 20;   // 16 + 4 pad (floats)
    const int LDB = 68;   // 64 + 4 pad
    __shared__ float As[128 * LDA];
    __shared__ float Bs[16 * LDB];
    __shared__ float stage[8][16 * 20];

    const int tid = threadIdx.x;
    const int warp = tid >> 5, lane = tid & 31;
    const int wm = warp >> 1, wn = warp & 1;
    const int row0 = blockIdx.y * 128;
    const int col0 = blockIdx.x * 64;

    wmma::fragment<wmma::accumulator, 16, 16, 8, float> acc[2][2];
#pragma unroll
    for (int i = 0; i < 2; i++)
#pragma unroll
        for (int j = 0; j < 2; j++) wmma::fill_fragment(acc[i][j], 0.f);

    for (int k0 = 0; k0 < K; k0 += 16) {
        // A tile: 128 rows x 16 k, 512 float4 -> 2 per thread
#pragma unroll
        for (int v = 0; v < 2; v++) {
            int idx = tid + v * 256;
            int r = idx >> 2, c4 = idx & 3;
            float4 val = make_float4(0.f, 0.f, 0.f, 0.f);
            if (row0 + r < M)
                val = *(const float4*)(A + (size_t)(row0 + r) * K + k0 + c4 * 4);
            float* d = As + r * LDA + c4 * 4;
            d[0] = to_tf32(val.x); d[1] = to_tf32(val.y);
            d[2] = to_tf32(val.z); d[3] = to_tf32(val.w);
        }
        // B tile: 16 k-rows x 64 cols, 256 float4 -> 1 per thread
        {
            int r = tid >> 4, c4 = tid & 15;
            int c = col0 + c4 * 4;
            float4 val = make_float4(0.f, 0.f, 0.f, 0.f);
            if (c + 3 < Nc) {
                val = *(const float4*)(B + (size_t)(k0 + r) * Nc + c);
            } else {
                const float* bp = B + (size_t)(k0 + r) * Nc;
                if (c + 0 < Nc) val.x = bp[c + 0];
                if (c + 1 < Nc) val.y = bp[c + 1];
                if (c + 2 < Nc) val.z = bp[c + 2];
                if (c + 3 < Nc) val.w = bp[c + 3];
            }
            float* d = Bs + r * LDB + c4 * 4;
            d[0] = to_tf32(val.x); d[1] = to_tf32(val.y);
            d[2] = to_tf32(val.z); d[3] = to_tf32(val.w);
        }
        __syncthreads();
#pragma unroll
        for (int ks = 0; ks < 16; ks += 8) {
            wmma::fragment<wmma::matrix_a, 16, 16, 8, wmma::precision::tf32,
                           wmma::row_major> fa[2];
            wmma::fragment<wmma::matrix_b, 16, 16, 8, wmma::precision::tf32,
                           wmma::row_major> fb[2];
#pragma unroll
            for (int i = 0; i < 2; i++)
                wmma::load_matrix_sync(fa[i], As + (wm * 32 + 16 * i) * LDA + ks, LDA);
#pragma unroll
            for (int j = 0; j < 2; j++)
                wmma::load_matrix_sync(fb[j], Bs + ks * LDB + wn * 32 + 16 * j, LDB);
#pragma unroll
            for (int i = 0; i < 2; i++)
#pragma unroll
                for (int j = 0; j < 2; j++)
                    wmma::mma_sync(acc[i][j], fa[i], fb[j], acc[i][j]);
        }
        __syncthreads();
    }

    const bool interior = (row0 + 128 <= M) && (col0 + 64 <= Nc);
    if (interior) {
#pragma unroll
        for (int i = 0; i < 2; i++)
#pragma unroll
            for (int j = 0; j < 2; j++) {
                float* cp = C + (size_t)(row0 + wm * 32 + 16 * i) * Nc
                              + col0 + wn * 32 + 16 * j;
                wmma::store_matrix_sync(cp, acc[i][j], Nc, wmma::mem_row_major);
            }
    } else {
#pragma unroll
        for (int i = 0; i < 2; i++)
#pragma unroll
            for (int j = 0; j < 2; j++) {
                wmma::store_matrix_sync(stage[warp], acc[i][j], 20, wmma::mem_row_major);
                __syncwarp();
#pragma unroll
                for (int e = 0; e < 8; e++) {
                    int idx = lane + e * 32;
                    int r = idx >> 4, c = idx & 15;
                    int gr = row0 + wm * 32 + 16 * i + r;
                    int gc = col0 + wn * 32 + 16 * j + c;
                    if (gr < M && gc < Nc)
                        C[(size_t)gr * Nc + gc] = stage[warp][r * 20 + c];
                }
                __syncwarp();
            }
    }
}

// final-linear bias add
__global__ void k_bias(float* __restrict__ out, const float* __restrict__ b) {
    int i = blockIdx.x * blockDim.x + threadIdx.x;
    if (i < NN * NCLS) out[i] += b[i & (NCLS - 1)];
}

// ---------------- attention projections ----------------
template<int C>
__global__ void k_att(const float* __restrict__ feat,
                      const float* __restrict__ a_src,
                      const float* __restrict__ a_dst,
                      float* __restrict__ asrc,
                      float* __restrict__ adst)
{
    int idx = blockIdx.x * blockDim.x + threadIdx.x;
    if (idx >= NN * NH) return;
    int n = idx >> 3, h = idx & 7;
    const float* fr = feat + (size_t)n * (NH * C) + h * C;
    float ss = 0.f, sd = 0.f;
#pragma unroll
    for (int c = 0; c < C; c++) {
        float f = fr[c];
        ss += f * a_src[h * C + c];
        sd += f * a_dst[h * C + c];
    }
    asrc[idx] = ss;
    adst[idx] = sd;
}

// ---------------- per-destination GAT aggregation ----------------
template<int C, bool ELU>
__global__ __launch_bounds__(256) void k_agg(
    const float* __restrict__ feat,
    const float* __restrict__ asrc,
    const float* __restrict__ adst,
    const float* __restrict__ bias,
    float* __restrict__ out)
{
    const int HC = NH * C;
    __shared__ float    s_adst[NH];
    __shared__ unsigned s_max[NH];
    __shared__ float    s_sum[NH];
    __shared__ int      s_src[64];
    __shared__ float    s_w[64 * NH];

    int n = blockIdx.x, tid = threadIdx.x;
    if (tid < NH) {
        s_adst[tid] = adst[n * NH + tid];
        s_max[tid]  = encodeF(-3.4e38f);
        s_sum[tid]  = 0.f;
    }
    __syncthreads();

    int base = g_off[n];
    int deg  = g_off[n + 1] - base;

    for (int i = tid; i < deg * NH; i += 256) {
        int j = i >> 3, h = i & 7;
        int s = g_csr[base + j];
        float al = asrc[s * NH + h] + s_adst[h];
        al = al > 0.f ? al : 0.2f * al;
        atomicMax(&s_max[h], encodeF(al));
    }
    __syncthreads();

    for (int i = tid; i < deg * NH; i += 256) {
        int j = i >> 3, h = i & 7;
        int s = g_csr[base + j];
        float al = asrc[s * NH + h] + s_adst[h];
        al = al > 0.f ? al : 0.2f * al;
        atomicAdd(&s_sum[h], __expf(al - decodeF(s_max[h])));
    }
    __syncthreads();

    int c0 = tid, c1 = tid + 256;
    int h0 = c0 / C, h1 = c1 / C;
    float acc0 = 0.f, acc1 = 0.f;

    for (int j0 = 0; j0 < deg; j0 += 64) {
        int nch = min(64, deg - j0);
        if (tid < nch) s_src[tid] = g_csr[base + j0 + tid];
        for (int i = tid; i < nch * NH; i += 256) {
            int j = i >> 3, h = i & 7;
            int s = g_csr[base + j0 + j];
            float al = asrc[s * NH + h] + s_adst[h];
            al = al > 0.f ? al : 0.2f * al;
            s_w[(j << 3) + h] = __expf(al - decodeF(s_max[h])) / (s_sum[h] + 1e-16f);
        }
        __syncthreads();
        for (int j = 0; j < nch; j++) {
            const float* fr = feat + (size_t)s_src[j] * HC;
            if (c0 < HC) acc0 += s_w[(j << 3) + h0] * fr[c0];
            if (HC > 256 && c1 < HC) acc1 += s_w[(j << 3) + h1] * fr[c1];
        }
        __syncthreads();
    }

    if (c0 < HC) {
        float v = acc0 + bias[c0];
        if (ELU) v = v > 0.f ? v : (__expf(v) - 1.f);
        out[(size_t)n * HC + c0] = v;
    }
    if (HC > 256 && c1 < HC) {
        float v = acc1 + bias[c1];
        if (ELU) v = v > 0.f ? v : (__expf(v) - 1.f);
        out[(size_t)n * HC + c1] = v;
    }
}

// ---------------- launch ----------------
extern "C" void kernel_launch(void* const* d_in, const int* in_sizes, int n_in,
                              void* d_out, int out_size)
{
    const float* x    = (const float*)d_in[0];
    const void*  eidx = d_in[1];
    const float* W1   = (const float*)d_in[2];
    const float* a1s  = (const float*)d_in[3];
    const float* a1d  = (const float*)d_in[4];
    const float* b1   = (const float*)d_in[5];
    const float* W2   = (const float*)d_in[6];
    const float* a2s  = (const float*)d_in[7];
    const float* a2d  = (const float*)d_in[8];
    const float* b2   = (const float*)d_in[9];
    const float* Wlin = (const float*)d_in[10];
    const float* blin = (const float*)d_in[11];

    float* out_cls = (float*)d_out;
    float* out_h   = out_cls + (size_t)NN * NCLS;

    void *p_feat1, *p_as1, *p_ad1, *p_h1, *p_feat2, *p_as2, *p_ad2;
    cudaGetSymbolAddress(&p_feat1, g_feat1);
    cudaGetSymbolAddress(&p_as1,   g_as1);
    cudaGetSymbolAddress(&p_ad1,   g_ad1);
    cudaGetSymbolAddress(&p_h1,    g_h1);
    cudaGetSymbolAddress(&p_feat2, g_feat2);
    cudaGetSymbolAddress(&p_as2,   g_as2);
    cudaGetSymbolAddress(&p_ad2,   g_ad2);

    const int T = 256;

    // graph preprocessing
    k_init   <<<(NN   + T - 1) / T, T>>>();
    k_detect <<<(EE   + T - 1) / T, T>>>((const int*)eidx);
    k_convert<<<(EE   + T - 1) / T, T>>>(eidx);
    k_count  <<<(EE   + T - 1) / T, T>>>();
    k_scan   <<<1, 256>>>();
    k_scatter<<<(ETOT + T - 1) / T, T>>>();

    // layer 1: feat1 = x @ W1
    {
        dim3 grid((HC1 + 63) / 64, (NN + 127) / 128);
        k_gemm_wmma<<<grid, 256>>>(x, W1, (float*)p_feat1, NN, HC1, FIN);
    }
    k_att<C1><<<(NN * NH + T - 1) / T, T>>>((const float*)p_feat1, a1s, a1d,
                                            (float*)p_as1, (float*)p_ad1);
    k_agg<C1, true><<<NN, 256>>>((const float*)p_feat1, (const float*)p_as1,
                                 (const float*)p_ad1, b1, (float*)p_h1);

    // layer 2: feat2 = h1 @ W2
    {
        dim3 grid((HC2 + 63) / 64, (NN + 127) / 128);
        k_gemm_wmma<<<grid, 256>>>((const float*)p_h1, W2, (float*)p_feat2,
                                   NN, HC2, HC1);
    }
    k_att<C2><<<(NN * NH + T - 1) / T, T>>>((const float*)p_feat2, a2s, a2d,
                                            (float*)p_as2, (float*)p_ad2);
    k_agg<C2, false><<<NN, 256>>>((const float*)p_feat2, (const float*)p_as2,
                                  (const float*)p_ad2, b2, out_h);

    // final linear: out = h @ Wlin + blin
    {
        dim3 grid((NCLS + 63) / 64, (NN + 127) / 128);
        k_gemm_wmma<<<grid, 256>>>(out_h, Wlin, out_cls, NN, NCLS, HC2);
    }
    k_bias<<<(NN * NCLS + T - 1) / T, T>>>(out_cls, blin);
}

// round 4
// speedup vs baseline: 1.2292x; 1.0500x over previous
#include <cuda_runtime.h>
#include <cuda_bf16.h>
#include <mma.h>
#include <math.h>
#include <cstdint>

using namespace nvcuda;

// ---------------- problem constants ----------------
#define NN      10000
#define EE      160000
#define ETOT    170000
#define NH      8
#define C1      30
#define C2      64
#define HC1     240
#define HC2     512
#define FIN     512
#define NCLS    64

// ---------------- device scratch ----------------
__device__ int   g_flag32;
__device__ int   g_src[EE];
__device__ int   g_dst[EE];
__device__ int   g_cnt[NN];
__device__ int   g_off[NN + 1];
__device__ int   g_cur[NN];
__device__ int   g_csr[ETOT];
__device__ float g_feat1[NN * HC1];
__device__ float g_as1[NN * NH];
__device__ float g_ad1[NN * NH];
__device__ float g_h1[NN * HC1];
__device__ float g_feat2[NN * HC2];
__device__ float g_as2[NN * NH];
__device__ float g_ad2[NN * NH];

// ---------------- helpers ----------------
__device__ __forceinline__ unsigned encodeF(float f) {
    unsigned u = __float_as_uint(f);
    return (u & 0x80000000u) ? ~u : (u | 0x80000000u);
}
__device__ __forceinline__ float decodeF(unsigned e) {
    return (e & 0x80000000u) ? __uint_as_float(e ^ 0x80000000u)
                             : __uint_as_float(~e);
}
__device__ __forceinline__ float to_tf32(float f) {
    float o;
    asm("cvt.rna.tf32.f32 %0, %1;" : "=f"(o) : "f"(f));
    return o;
}

// ---------------- graph preprocessing (fused) ----------------
__global__ void k_pre1(const int* __restrict__ e32) {
    int i = blockIdx.x * blockDim.x + threadIdx.x;
    if (i < NN) g_cnt[i] = 1;              // self loop
    if (i == 0) {
        int f = 0;
#pragma unroll
        for (int t = 0; t < 64; t++) f |= e32[2 * t + 1];
        g_flag32 = (f != 0);               // any nonzero odd word => int32 layout
    }
}
__global__ void k_pre2(const void* __restrict__ eraw) {
    int i = blockIdx.x * blockDim.x + threadIdx.x;
    if (i >= EE) return;
    int s, d;
    if (g_flag32) {
        const int* p = (const int*)eraw;
        s = p[i]; d = p[EE + i];
    } else {
        const long long* p = (const long long*)eraw;
        s = (int)p[i]; d = (int)p[EE + i];
    }
    g_src[i] = s;
    g_dst[i] = d;
    atomicAdd(&g_cnt[d], 1);
}
__global__ void k_scan() {
    __shared__ int ps[257];
    const int CHUNK = 40;
    int t = threadIdx.x;
    int s = 0;
    for (int k = 0; k < CHUNK; k++) {
        int idx = t * CHUNK + k;
        if (idx < NN) s += g_cnt[idx];
    }
    ps[t] = s;
    __syncthreads();
    if (t == 0) {
        int run = 0;
        for (int i = 0; i < 256; i++) { int tmp = ps[i]; ps[i] = run; run += tmp; }
        ps[256] = run;
    }
    __syncthreads();
    int run = ps[t];
    for (int k = 0; k < CHUNK; k++) {
        int idx = t * CHUNK + k;
        if (idx < NN) {
            g_off[idx] = run;
            g_cur[idx] = run;
            run += g_cnt[idx];
        }
    }
    if (t == 0) g_off[NN] = ps[256];
}
__global__ void k_scatter() {
    int i = blockIdx.x * blockDim.x + threadIdx.x;
    if (i >= ETOT) return;
    int d, s;
    if (i < EE) { d = g_dst[i]; s = g_src[i]; }
    else        { d = i - EE;   s = d; }
    int pos = atomicAdd(&g_cur[d], 1);
    g_csr[pos] = s;
}

// ---------------- pipelined tf32 WMMA GEMM ----------------
// C[M,Nc] = A[M,K] @ B[K,Nc] (+bias via acc init). BM=64*FM, BN=64, BK=16.
// 8 warps (4 in M, 2 in N); warp tile (16*FM)x32. K % 16 == 0.
template<int FM>
__global__ __launch_bounds__(256) void k_gemm(
    const float* __restrict__ A, const float* __restrict__ B,
    float* __restrict__ C, int M, int Nc, int K,
    const float* __restrict__ bias)
{
    constexpr int BM  = 64 * FM;
    constexpr int LDA = 20;
    constexpr int LDB = 68;
    __shared__ float As[2][BM * LDA];
    __shared__ float Bs[2][16 * LDB];
    __shared__ float stage[8][16 * 20];

    const int tid  = threadIdx.x;
    const int warp = tid >> 5, lane = tid & 31;
    const int wm = warp >> 1, wn = warp & 1;
    const int row0 = blockIdx.y * BM;
    const int col0 = blockIdx.x * 64;

    wmma::fragment<wmma::accumulator, 16, 16, 8, float> acc[FM][2];

    if (bias) {
        // init accumulators with replicated bias rows (same for every M row)
#pragma unroll
        for (int j = 0; j < 2; j++) {
#pragma unroll
            for (int e = 0; e < 8; e++) {
                int idx = lane + e * 32;
                int r = idx >> 4, c = idx & 15;
                int gc = col0 + wn * 32 + 16 * j + c;
                stage[warp][r * 20 + c] = (gc < Nc) ? bias[gc] : 0.f;
            }
            __syncwarp();
#pragma unroll
            for (int i = 0; i < FM; i++)
                wmma::load_matrix_sync(acc[i][j], stage[warp], 20,
                                       wmma::mem_row_major);
            __syncwarp();
        }
    } else {
#pragma unroll
        for (int i = 0; i < FM; i++)
#pragma unroll
            for (int j = 0; j < 2; j++) wmma::fill_fragment(acc[i][j], 0.f);
    }

    float4 ra[FM];
    float4 rb;
    const int nk = K / 16;

#define LOAD_T(K0) do {                                                      \
        int kk = (K0);                                                       \
        _Pragma("unroll")                                                    \
        for (int v = 0; v < FM; v++) {                                       \
            int idx = tid + v * 256;                                         \
            int r = idx >> 2, c4 = idx & 3;                                  \
            ra[v] = make_float4(0.f, 0.f, 0.f, 0.f);                         \
            if (row0 + r < M)                                                \
                ra[v] = *(const float4*)(A + (size_t)(row0 + r) * K + kk + c4 * 4); \
        }                                                                    \
        {                                                                    \
            int r = tid >> 4, c4 = tid & 15;                                 \
            int c = col0 + c4 * 4;                                           \
            rb = make_float4(0.f, 0.f, 0.f, 0.f);                            \
            if (c + 3 < Nc) {                                                \
                rb = *(const float4*)(B + (size_t)(kk + r) * Nc + c);        \
            } else {                                                         \
                const float* bp = B + (size_t)(kk + r) * Nc;                 \
                if (c + 0 < Nc) rb.x = bp[c + 0];                            \
                if (c + 1 < Nc) rb.y = bp[c + 1];                            \
                if (c + 2 < Nc) rb.z = bp[c + 2];                            \
            }                                                                \
        }                                                                    \
    } while (0)

#define STORE_T(BUF) do {                                                    \
        _Pragma("unroll")                                                    \
        for (int v = 0; v < FM; v++) {                                       \
            int idx = tid + v * 256;                                         \
            int r = idx >> 2, c4 = idx & 3;                                  \
            float* d = &As[BUF][r * LDA + c4 * 4];                           \
            d[0] = to_tf32(ra[v].x); d[1] = to_tf32(ra[v].y);                \
            d[2] = to_tf32(ra[v].z); d[3] = to_tf32(ra[v].w);                \
        }                                                                    \
        {                                                                    \
            int r = tid >> 4, c4 = tid & 15;                                 \
            float* d = &Bs[BUF][r * LDB + c4 * 4];                           \
            d[0] = to_tf32(rb.x); d[1] = to_tf32(rb.y);                      \
            d[2] = to_tf32(rb.z); d[3] = to_tf32(rb.w);                      \
        }                                                                    \
    } while (0)

    LOAD_T(0);
    STORE_T(0);
    __syncthreads();

    for (int it = 0; it < nk; it++) {
        if (it + 1 < nk) LOAD_T((it + 1) * 16);
        const int cur = it & 1;
#pragma unroll
        for (int ks = 0; ks < 16; ks += 8) {
            wmma::fragment<wmma::matrix_a, 16, 16, 8, wmma::precision::tf32,
                           wmma::row_major> fa[FM];
            wmma::fragment<wmma::matrix_b, 16, 16, 8, wmma::precision::tf32,
                           wmma::row_major> fb[2];
#pragma unroll
            for (int i = 0; i < FM; i++)
                wmma::load_matrix_sync(fa[i],
                    &As[cur][(wm * 16 * FM + 16 * i) * LDA + ks], LDA);
#pragma unroll
            for (int j = 0; j < 2; j++)
                wmma::load_matrix_sync(fb[j],
                    &Bs[cur][ks * LDB + wn * 32 + 16 * j], LDB);
#pragma unroll
            for (int i = 0; i < FM; i++)
#pragma unroll
                for (int j = 0; j < 2; j++)
                    wmma::mma_sync(acc[i][j], fa[i], fb[j], acc[i][j]);
        }
        if (it + 1 < nk) STORE_T((it + 1) & 1);
        __syncthreads();
    }
#undef LOAD_T
#undef STORE_T

    const bool interior = (row0 + BM <= M) && (col0 + 64 <= Nc);
    if (interior) {
#pragma unroll
        for (int i = 0; i < FM; i++)
#pragma unroll
            for (int j = 0; j < 2; j++) {
                float* cp = C + (size_t)(row0 + wm * 16 * FM + 16 * i) * Nc
                              + col0 + wn * 32 + 16 * j;
                wmma::store_matrix_sync(cp, acc[i][j], Nc, wmma::mem_row_major);
            }
    } else {
#pragma unroll
        for (int i = 0; i < FM; i++)
#pragma unroll
            for (int j = 0; j < 2; j++) {
                wmma::store_matrix_sync(stage[warp], acc[i][j], 20,
                                        wmma::mem_row_major);
                __syncwarp();
#pragma unroll
                for (int e = 0; e < 8; e++) {
                    int idx = lane + e * 32;
                    int r = idx >> 4, c = idx & 15;
                    int gr = row0 + wm * 16 * FM + 16 * i + r;
                    int gc = col0 + wn * 32 + 16 * j + c;
                    if (gr < M && gc < Nc)
                        C[(size_t)gr * Nc + gc] = stage[warp][r * 20 + c];
                }
                __syncwarp();
            }
    }
}

// ---------------- attention projections ----------------
template<int C>
__global__ void k_att(const float* __restrict__ feat,
                      const float* __restrict__ a_src,
                      const float* __restrict__ a_dst,
                      float* __restrict__ asrc,
                      float* __restrict__ adst)
{
    int idx = blockIdx.x * blockDim.x + threadIdx.x;
    if (idx >= NN * NH) return;
    int n = idx >> 3, h = idx & 7;
    const float* fr = feat + (size_t)n * (NH * C) + h * C;
    float ss = 0.f, sd = 0.f;
#pragma unroll
    for (int c = 0; c < C; c++) {
        float f = fr[c];
        ss += f * a_src[h * C + c];
        sd += f * a_dst[h * C + c];
    }
    asrc[idx] = ss;
    adst[idx] = sd;
}

// ---------------- per-destination GAT aggregation ----------------
template<int C, bool ELU>
__global__ __launch_bounds__(256) void k_agg(
    const float* __restrict__ feat,
    const float* __restrict__ asrc,
    const float* __restrict__ adst,
    const float* __restrict__ bias,
    float* __restrict__ out)
{
    const int HC = NH * C;
    __shared__ float    s_adst[NH];
    __shared__ unsigned s_max[NH];
    __shared__ float    s_sum[NH];
    __shared__ float    s_rs[NH];
    __shared__ int      s_src[64];
    __shared__ float    s_w[64 * NH];

    int n = blockIdx.x, tid = threadIdx.x;
    if (tid < NH) {
        s_adst[tid] = adst[n * NH + tid];
        s_max[tid]  = encodeF(-3.4e38f);
        s_sum[tid]  = 0.f;
    }
    __syncthreads();

    int base = g_off[n];
    int deg  = g_off[n + 1] - base;

    int c0 = tid, c1 = tid + 256;
    int h0 = c0 / C, h1 = c1 / C;
    float acc0 = 0.f, acc1 = 0.f;

    if (deg <= 64) {
        // ---- fast path: weights cached in smem ----
        if (tid < deg) s_src[tid] = g_csr[base + tid];
        __syncthreads();
        for (int i = tid; i < deg * NH; i += 256) {
            int j = i >> 3, h = i & 7;
            float al = asrc[s_src[j] * NH + h] + s_adst[h];
            al = al > 0.f ? al : 0.2f * al;
            s_w[i] = al;                        // stash alpha
            atomicMax(&s_max[h], encodeF(al));
        }
        __syncthreads();
        for (int i = tid; i < deg * NH; i += 256) {
            int h = i & 7;
            float e = __expf(s_w[i] - decodeF(s_max[h]));
            s_w[i] = e;
            atomicAdd(&s_sum[h], e);
        }
        __syncthreads();
        if (tid < NH) s_rs[tid] = 1.f / (s_sum[tid] + 1e-16f);
        __syncthreads();

        int j = 0;
        for (; j + 1 < deg; j += 2) {
            const float* f0 = feat + (size_t)s_src[j] * HC;
            const float* f1 = feat + (size_t)s_src[j + 1] * HC;
            float w0a = s_w[(j << 3) + h0]     * s_rs[h0];
            float w1a = s_w[((j + 1) << 3) + h0] * s_rs[h0];
            if (c0 < HC) acc0 += w0a * f0[c0] + w1a * f1[c0];
            if (HC > 256 && c1 < HC) {
                float w0b = s_w[(j << 3) + h1]     * s_rs[h1];
                float w1b = s_w[((j + 1) << 3) + h1] * s_rs[h1];
                acc1 += w0b * f0[c1] + w1b * f1[c1];
            }
        }
        if (j < deg) {
            const float* f0 = feat + (size_t)s_src[j] * HC;
            if (c0 < HC) acc0 += s_w[(j << 3) + h0] * s_rs[h0] * f0[c0];
            if (HC > 256 && c1 < HC) acc1 += s_w[(j << 3) + h1] * s_rs[h1] * f0[c1];
        }
    } else {
        // ---- general path (recompute weights per chunk) ----
        for (int i = tid; i < deg * NH; i += 256) {
            int j = i >> 3, h = i & 7;
            float al = asrc[g_csr[base + j] * NH + h] + s_adst[h];
            al = al > 0.f ? al : 0.2f * al;
            atomicMax(&s_max[h], encodeF(al));
        }
        __syncthreads();
        for (int i = tid; i < deg * NH; i += 256) {
            int j = i >> 3, h = i & 7;
            float al = asrc[g_csr[base + j] * NH + h] + s_adst[h];
            al = al > 0.f ? al : 0.2f * al;
            atomicAdd(&s_sum[h], __expf(al - decodeF(s_max[h])));
        }
        __syncthreads();
        if (tid < NH) s_rs[tid] = 1.f / (s_sum[tid] + 1e-16f);
        __syncthreads();
        for (int j0 = 0; j0 < deg; j0 += 64) {
            int nch = min(64, deg - j0);
            if (tid < nch) s_src[tid] = g_csr[base + j0 + tid];
            for (int i = tid; i < nch * NH; i += 256) {
                int j = i >> 3, h = i & 7;
                float al = asrc[g_csr[base + j0 + j] * NH + h] + s_adst[h];
                al = al > 0.f ? al : 0.2f * al;
                s_w[i] = __expf(al - decodeF(s_max[h])) * s_rs[h];
            }
            __syncthreads();
            for (int j = 0; j < nch; j++) {
                const float* fr = feat + (size_t)s_src[j] * HC;
                if (c0 < HC) acc0 += s_w[(j << 3) + h0] * fr[c0];
                if (HC > 256 && c1 < HC) acc1 += s_w[(j << 3) + h1] * fr[c1];
            }
            __syncthreads();
        }
    }

    if (c0 < HC) {
        float v = acc0 + bias[c0];
        if (ELU) v = v > 0.f ? v : (__expf(v) - 1.f);
        out[(size_t)n * HC + c0] = v;
    }
    if (HC > 256 && c1 < HC) {
        float v = acc1 + bias[c1];
        if (ELU) v = v > 0.f ? v : (__expf(v) - 1.f);
        out[(size_t)n * HC + c1] = v;
    }
}

// ---------------- launch ----------------
extern "C" void kernel_launch(void* const* d_in, const int* in_sizes, int n_in,
                              void* d_out, int out_size)
{
    const float* x    = (const float*)d_in[0];
    const void*  eidx = d_in[1];
    const float* W1   = (const float*)d_in[2];
    const float* a1s  = (const float*)d_in[3];
    const float* a1d  = (const float*)d_in[4];
    const float* b1   = (const float*)d_in[5];
    const float* W2   = (const float*)d_in[6];
    const float* a2s  = (const float*)d_in[7];
    const float* a2d  = (const float*)d_in[8];
    const float* b2   = (const float*)d_in[9];
    const float* Wlin = (const float*)d_in[10];
    const float* blin = (const float*)d_in[11];

    float* out_cls = (float*)d_out;
    float* out_h   = out_cls + (size_t)NN * NCLS;

    void *p_feat1, *p_as1, *p_ad1, *p_h1, *p_feat2, *p_as2, *p_ad2;
    cudaGetSymbolAddress(&p_feat1, g_feat1);
    cudaGetSymbolAddress(&p_as1,   g_as1);
    cudaGetSymbolAddress(&p_ad1,   g_ad1);
    cudaGetSymbolAddress(&p_h1,    g_h1);
    cudaGetSymbolAddress(&p_feat2, g_feat2);
    cudaGetSymbolAddress(&p_as2,   g_as2);
    cudaGetSymbolAddress(&p_ad2,   g_ad2);

    const int T = 256;

    // graph preprocessing
    k_pre1   <<<(NN   + T - 1) / T, T>>>((const int*)eidx);
    k_pre2   <<<(EE   + T - 1) / T, T>>>(eidx);
    k_scan   <<<1, 256>>>();
    k_scatter<<<(ETOT + T - 1) / T, T>>>();

    // layer 1: feat1 = x @ W1
    {
        dim3 grid((HC1 + 63) / 64, (NN + 127) / 128);
        k_gemm<2><<<grid, 256>>>(x, W1, (float*)p_feat1, NN, HC1, FIN, nullptr);
    }
    k_att<C1><<<(NN * NH + T - 1) / T, T>>>((const float*)p_feat1, a1s, a1d,
                                            (float*)p_as1, (float*)p_ad1);
    k_agg<C1, true><<<NN, 256>>>((const float*)p_feat1, (const float*)p_as1,
                                 (const float*)p_ad1, b1, (float*)p_h1);

    // layer 2: feat2 = h1 @ W2
    {
        dim3 grid((HC2 + 63) / 64, (NN + 127) / 128);
        k_gemm<2><<<grid, 256>>>((const float*)p_h1, W2, (float*)p_feat2,
                                 NN, HC2, HC1, nullptr);
    }
    k_att<C2><<<(NN * NH + T - 1) / T, T>>>((const float*)p_feat2, a2s, a2d,
                                            (float*)p_as2, (float*)p_ad2);
    k_agg<C2, false><<<NN, 256>>>((const float*)p_feat2, (const float*)p_as2,
                                  (const float*)p_ad2, b2, out_h);

    // final linear: out = h @ Wlin + blin  (bias folded into acc init)
    {
        dim3 grid((NCLS + 63) / 64, (NN + 63) / 64);
        k_gemm<1><<<grid, 256>>>(out_h, Wlin, out_cls, NN, NCLS, HC2, blin);
    }
}